// round 1
// baseline (speedup 1.0000x reference)
#include <cuda_runtime.h>

#define NB 8192
#define ND 512

__device__ float g_inv[NB];   // 1/||x_i||
__device__ float g_sq[NB];    // sum(n_i^2) computed like the reference
__device__ float g_acc;      // global accumulator

// ---------------------------------------------------------------------------
// Kernel 1: per-row norms. One 256-thread block per row (2 elems/thread).
// Also zeroes g_acc (row 0's block), which is safe: kernel1 fully completes
// before kernel2 starts (stream order), and it re-zeroes on every graph replay.
// ---------------------------------------------------------------------------
__global__ __launch_bounds__(256) void prep_kernel(const float* __restrict__ x) {
    int row = blockIdx.x;
    const float* xr = x + (size_t)row * ND;
    int tid = threadIdx.x;

    float v0 = xr[tid];
    float v1 = xr[tid + 256];
    float s = v0 * v0 + v1 * v1;

    __shared__ float red[8];
    #pragma unroll
    for (int o = 16; o; o >>= 1) s += __shfl_xor_sync(0xffffffffu, s, o);
    if ((tid & 31) == 0) red[tid >> 5] = s;
    __syncthreads();
    if (tid == 0) {
        float t = 0.f;
        #pragma unroll
        for (int i = 0; i < 8; i++) t += red[i];
        red[0] = t;
    }
    __syncthreads();
    float inv = 1.0f / sqrtf(red[0]);

    // sq = sum((x*inv)^2), elementwise like the reference's sum(n*n)
    float n0 = v0 * inv, n1 = v1 * inv;
    float sq = n0 * n0 + n1 * n1;
    __shared__ float red2[8];
    #pragma unroll
    for (int o = 16; o; o >>= 1) sq += __shfl_xor_sync(0xffffffffu, sq, o);
    if ((tid & 31) == 0) red2[tid >> 5] = sq;
    __syncthreads();
    if (tid == 0) {
        float t = 0.f;
        #pragma unroll
        for (int i = 0; i < 8; i++) t += red2[i];
        g_sq[row] = t;
        g_inv[row] = inv;
        if (row == 0) g_acc = 0.f;
    }
}

// ---------------------------------------------------------------------------
// Kernel 2: tiled SGEMM on raw x, fused loss epilogue.
// Grid 64x64; blocks with bj < bi (strict lower triangle of tiles) exit.
// Each block: 128x128 tile of G = x x^T, scaled by inv_i*inv_j in epilogue.
// ---------------------------------------------------------------------------
#define BM 128
#define BN 128
#define BK 16
#define TM 8
#define TN 8

__global__ __launch_bounds__(256) void gemm_loss_kernel(
    const float* __restrict__ x,
    const long long* __restrict__ y)
{
    const int bi = blockIdx.x;   // tile row block (i)
    const int bj = blockIdx.y;   // tile col block (j)
    if (bj < bi) return;

    __shared__ float As[BK][BM];
    __shared__ float Bs[BK][BN];

    const int tid = threadIdx.x;
    const int tx = tid & 15;     // 0..15  (N direction)
    const int ty = tid >> 4;     // 0..15  (M direction)

    float c[TM][TN];
    #pragma unroll
    for (int a = 0; a < TM; a++)
        #pragma unroll
        for (int b = 0; b < TN; b++) c[a][b] = 0.f;

    const float* Aptr = x + (size_t)bi * BM * ND;
    const float* Bptr = x + (size_t)bj * BN * ND;

    // Load mapping: 128 rows x 16 cols per tile = 2048 floats, 256 threads, 8 each.
    const int lr = tid >> 1;          // row in tile 0..127
    const int lc = (tid & 1) * 8;     // col offset 0 or 8

    const float* aRow = Aptr + (size_t)lr * ND + lc;
    const float* bRow = Bptr + (size_t)lr * ND + lc;

    for (int k0 = 0; k0 < ND; k0 += BK) {
        float4 a0 = *(const float4*)(aRow + k0);
        float4 a1 = *(const float4*)(aRow + k0 + 4);
        float4 b0 = *(const float4*)(bRow + k0);
        float4 b1 = *(const float4*)(bRow + k0 + 4);

        __syncthreads();   // previous compute done before overwriting smem
        As[lc + 0][lr] = a0.x; As[lc + 1][lr] = a0.y;
        As[lc + 2][lr] = a0.z; As[lc + 3][lr] = a0.w;
        As[lc + 4][lr] = a1.x; As[lc + 5][lr] = a1.y;
        As[lc + 6][lr] = a1.z; As[lc + 7][lr] = a1.w;
        Bs[lc + 0][lr] = b0.x; Bs[lc + 1][lr] = b0.y;
        Bs[lc + 2][lr] = b0.z; Bs[lc + 3][lr] = b0.w;
        Bs[lc + 4][lr] = b1.x; Bs[lc + 5][lr] = b1.y;
        Bs[lc + 6][lr] = b1.z; Bs[lc + 7][lr] = b1.w;
        __syncthreads();

        #pragma unroll
        for (int kk = 0; kk < BK; kk++) {
            float4 af0 = *(const float4*)&As[kk][ty * TM];
            float4 af1 = *(const float4*)&As[kk][ty * TM + 4];
            float4 bf0 = *(const float4*)&Bs[kk][tx * TN];
            float4 bf1 = *(const float4*)&Bs[kk][tx * TN + 4];
            float a_frag[TM] = {af0.x, af0.y, af0.z, af0.w, af1.x, af1.y, af1.z, af1.w};
            float b_frag[TN] = {bf0.x, bf0.y, bf0.z, bf0.w, bf1.x, bf1.y, bf1.z, bf1.w};
            #pragma unroll
            for (int a = 0; a < TM; a++)
                #pragma unroll
                for (int b = 0; b < TN; b++)
                    c[a][b] += a_frag[a] * b_frag[b];
        }
    }

    // ---- epilogue: load per-row metadata, fuse loss, reduce ----
    __shared__ float invA[BM], invB[BN], sqA[BM], sqB[BN];
    __shared__ long long yA[BM], yB[BN];
    __syncthreads();
    if (tid < 128) {
        int gi = bi * BM + tid;
        int gj = bj * BN + tid;
        invA[tid] = g_inv[gi]; sqA[tid] = g_sq[gi]; yA[tid] = y[gi];
        invB[tid] = g_inv[gj]; sqB[tid] = g_sq[gj]; yB[tid] = y[gj];
    }
    __syncthreads();

    const float THETA = 1.2f;
    const float XI    = 0.3f;

    float local = 0.f;
    #pragma unroll
    for (int a = 0; a < TM; a++) {
        int i  = ty * TM + a;
        int gi = bi * BM + i;
        float sqi  = sqA[i];
        float invi = invA[i];
        long long yi = yA[i];
        #pragma unroll
        for (int b = 0; b < TN; b++) {
            int j  = tx * TN + b;
            int gj = bj * BN + j;
            if (gj >= gi) {
                float g     = c[a][b] * invi * invB[j];
                float dist2 = sqi + sqB[j] - 2.0f * g;
                float hinge = fmaxf(THETA - dist2, 0.0f);
                float ind   = (yi == yB[j]) ? 1.0f : -1.0f;
                local += XI + ind * hinge;
            }
        }
    }

    #pragma unroll
    for (int o = 16; o; o >>= 1) local += __shfl_xor_sync(0xffffffffu, local, o);
    __shared__ float redr[8];
    if ((tid & 31) == 0) redr[tid >> 5] = local;
    __syncthreads();
    if (tid == 0) {
        float t = 0.f;
        #pragma unroll
        for (int i = 0; i < 8; i++) t += redr[i];
        atomicAdd(&g_acc, t);
    }
}

// ---------------------------------------------------------------------------
// Kernel 3: finalize
// ---------------------------------------------------------------------------
__global__ void finalize_kernel(float* out) {
    const double m = 1.0 / ((double)NB * (double)NB - (double)NB);
    out[0] = (float)(g_acc * m);
}

extern "C" void kernel_launch(void* const* d_in, const int* in_sizes, int n_in,
                              void* d_out, int out_size) {
    const float*     x = (const float*)d_in[0];
    const long long* y = (const long long*)d_in[1];
    float* out = (float*)d_out;

    prep_kernel<<<NB, 256>>>(x);
    dim3 grid(NB / BM, NB / BN);
    gemm_loss_kernel<<<grid, 256>>>(x, y);
    finalize_kernel<<<1, 1>>>(out);
}

// round 5
// speedup vs baseline: 5.9098x; 5.9098x over previous
#include <cuda_runtime.h>
#include <cuda_bf16.h>
#include <cstdint>

#define NB 8192
#define ND 512
#define BM 128
#define BK 32
#define NTILE (NB / BM)                  // 64
#define NPAIR (NTILE * (NTILE + 1) / 2)  // 2080
#define SSTRIDE 40                       // bf16 elems per smem row (80 bytes)

__device__ float g_inv[NB];
__device__ float g_sq[NB];
__device__ float g_acc;
__device__ __nv_bfloat16 g_xbf[(size_t)NB * ND];

__device__ __forceinline__ uint32_t smem_to_u32(const void* p) {
    uint32_t a;
    asm("{ .reg .u64 t; cvta.to.shared.u64 t, %1; cvt.u32.u64 %0, t; }" : "=r"(a) : "l"(p));
    return a;
}
__device__ __forceinline__ void cp_async16(uint32_t saddr, const void* gaddr) {
    asm volatile("cp.async.cg.shared.global [%0], [%1], 16;" :: "r"(saddr), "l"(gaddr) : "memory");
}
__device__ __forceinline__ void ldmx4(uint32_t* r, uint32_t addr) {
    asm volatile("ldmatrix.sync.aligned.m8n8.x4.shared.b16 {%0,%1,%2,%3}, [%4];"
                 : "=r"(r[0]), "=r"(r[1]), "=r"(r[2]), "=r"(r[3]) : "r"(addr));
}
__device__ __forceinline__ void mma16816(float* c, const uint32_t* a, uint32_t b0, uint32_t b1) {
    asm volatile(
        "mma.sync.aligned.m16n8k16.row.col.f32.bf16.bf16.f32 "
        "{%0,%1,%2,%3}, {%4,%5,%6,%7}, {%8,%9}, {%0,%1,%2,%3};"
        : "+f"(c[0]), "+f"(c[1]), "+f"(c[2]), "+f"(c[3])
        : "r"(a[0]), "r"(a[1]), "r"(a[2]), "r"(a[3]), "r"(b0), "r"(b1));
}

// ---------------------------------------------------------------------------
// Kernel 1: fused norms + fp32->bf16 conversion. One warp per row.
// ---------------------------------------------------------------------------
__global__ __launch_bounds__(256) void prep_convert(const float* __restrict__ x) {
    int row = blockIdx.x * 8 + (threadIdx.x >> 5);
    int lane = threadIdx.x & 31;
    const float4* xr = (const float4*)(x + (size_t)row * ND) + lane * 4;
    float4 v[4];
    v[0] = xr[0]; v[1] = xr[1]; v[2] = xr[2]; v[3] = xr[3];

    float s = 0.f;
    #pragma unroll
    for (int i = 0; i < 4; i++)
        s += v[i].x * v[i].x + v[i].y * v[i].y + v[i].z * v[i].z + v[i].w * v[i].w;
    #pragma unroll
    for (int o = 16; o; o >>= 1) s += __shfl_xor_sync(0xffffffffu, s, o);

    float inv = 1.0f / sqrtf(s);

    float sq = 0.f;
    #pragma unroll
    for (int i = 0; i < 4; i++) {
        float a = v[i].x * inv, b = v[i].y * inv, c = v[i].z * inv, d = v[i].w * inv;
        sq += a * a + b * b + c * c + d * d;
    }
    #pragma unroll
    for (int o = 16; o; o >>= 1) sq += __shfl_xor_sync(0xffffffffu, sq, o);

    if (lane == 0) {
        g_inv[row] = inv;
        g_sq[row] = sq;
        if (row == 0) g_acc = 0.f;
    }

    uint32_t u[8];
    #pragma unroll
    for (int i = 0; i < 4; i++) {
        __nv_bfloat162 p0 = __floats2bfloat162_rn(v[i].x, v[i].y);
        __nv_bfloat162 p1 = __floats2bfloat162_rn(v[i].z, v[i].w);
        u[2 * i]     = *reinterpret_cast<uint32_t*>(&p0);
        u[2 * i + 1] = *reinterpret_cast<uint32_t*>(&p1);
    }
    uint4* dst = (uint4*)(g_xbf + (size_t)row * ND + lane * 16);
    dst[0] = make_uint4(u[0], u[1], u[2], u[3]);
    dst[1] = make_uint4(u[4], u[5], u[6], u[7]);
}

// ---------------------------------------------------------------------------
// Kernel 2: bf16 mma.sync GEMM over upper-triangle tile pairs, fused epilogue.
// 256 threads = 8 warps (4 M x 2 N). Warp tile 32x64. Double-buffered cp.async.
// ---------------------------------------------------------------------------
__global__ __launch_bounds__(256, 2) void gemm_loss(const long long* __restrict__ y) {
    __shared__ __nv_bfloat16 sA[2][BM * SSTRIDE];
    __shared__ __nv_bfloat16 sB[2][BM * SSTRIDE];
    __shared__ float invA_s[BM], sqA_s[BM], invB_s[BM], sqB_s[BM];
    __shared__ long long yA_s[BM], yB_s[BM];
    __shared__ float redr[8];

    // decode upper-triangle pair (bi, bj)
    int t = blockIdx.x, bi = 0;
    while (t >= NTILE - bi) { t -= NTILE - bi; bi++; }
    const int bj = bi + t;

    const int tid = threadIdx.x;
    const int lane = tid & 31;
    const int wid = tid >> 5;
    const int wm = wid & 3;     // 0..3  -> 32-row slab
    const int wn = wid >> 2;    // 0..1  -> 64-col slab

    const uint32_t uA[2] = { smem_to_u32(sA[0]), smem_to_u32(sA[1]) };
    const uint32_t uB[2] = { smem_to_u32(sB[0]), smem_to_u32(sB[1]) };

    // epilogue metadata loads (overlap with pipeline prologue)
    if (tid < BM) {
        int gi = bi * BM + tid, gj = bj * BM + tid;
        invA_s[tid] = g_inv[gi]; sqA_s[tid] = g_sq[gi]; yA_s[tid] = y[gi];
        invB_s[tid] = g_inv[gj]; sqB_s[tid] = g_sq[gj]; yB_s[tid] = y[gj];
    }

    // global load mapping: each thread owns one smem row-half (32B = 2 chunks)
    const int lrow = tid >> 1;
    const int lc0 = (tid & 1) * 2;                 // chunk index 0 or 2
    const __nv_bfloat16* gA = g_xbf + (size_t)(bi * BM + lrow) * ND + lc0 * 8;
    const __nv_bfloat16* gB = g_xbf + (size_t)(bj * BM + lrow) * ND + lc0 * 8;
    const uint32_t soff = lrow * (SSTRIDE * 2) + lc0 * 16;

    // ldmatrix lane address components
    const int lg = lane >> 3, lr = lane & 7;
    // A x4: m0 rows+0/k0, m1 rows+8/k0, m2 rows+0/k8, m3 rows+8/k8
    const uint32_t aoff = (uint32_t)(wm * 32 + lr + ((lg & 1) * 8)) * (SSTRIDE * 2)
                        + ((lg >> 1) * 8) * 2;
    // B x4: m0 n+0/k0, m1 n+0/k8, m2 n+8/k0, m3 n+8/k8
    const uint32_t boff = (uint32_t)(wn * 64 + lr + ((lg >> 1) * 8)) * (SSTRIDE * 2)
                        + ((lg & 1) * 8) * 2;

    float c[2][8][4];
    #pragma unroll
    for (int mt = 0; mt < 2; mt++)
        #pragma unroll
        for (int nt = 0; nt < 8; nt++)
            #pragma unroll
            for (int r = 0; r < 4; r++) c[mt][nt][r] = 0.f;

    const int NK = ND / BK;   // 16

    // prologue: load k=0 into stage 0
    {
        cp_async16(uA[0] + soff,      gA);
        cp_async16(uA[0] + soff + 16, gA + 8);
        cp_async16(uB[0] + soff,      gB);
        cp_async16(uB[0] + soff + 16, gB + 8);
        asm volatile("cp.async.commit_group;" ::: "memory");
    }

    for (int k = 0; k < NK; k++) {
        const int b = k & 1;
        if (k + 1 < NK) {
            const int nb = b ^ 1;
            const __nv_bfloat16* ga = gA + (k + 1) * BK;
            const __nv_bfloat16* gb = gB + (k + 1) * BK;
            cp_async16(uA[nb] + soff,      ga);
            cp_async16(uA[nb] + soff + 16, ga + 8);
            cp_async16(uB[nb] + soff,      gb);
            cp_async16(uB[nb] + soff + 16, gb + 8);
            asm volatile("cp.async.commit_group;" ::: "memory");
            asm volatile("cp.async.wait_group 1;" ::: "memory");
        } else {
            asm volatile("cp.async.wait_group 0;" ::: "memory");
        }
        __syncthreads();

        #pragma unroll
        for (int ks = 0; ks < 2; ks++) {
            uint32_t af[2][4], bf[4][4];
            #pragma unroll
            for (int mt = 0; mt < 2; mt++)
                ldmx4(af[mt], uA[b] + aoff + mt * 16 * (SSTRIDE * 2) + ks * 32);
            #pragma unroll
            for (int p = 0; p < 4; p++)
                ldmx4(bf[p], uB[b] + boff + p * 16 * (SSTRIDE * 2) + ks * 32);
            #pragma unroll
            for (int mt = 0; mt < 2; mt++)
                #pragma unroll
                for (int nt = 0; nt < 8; nt++)
                    mma16816(c[mt][nt], af[mt], bf[nt >> 1][(nt & 1) * 2],
                             bf[nt >> 1][(nt & 1) * 2 + 1]);
        }
        __syncthreads();   // compute done before next iter overwrites stage b
    }

    // ---- fused loss epilogue on register fragments ----
    const int quad = lane >> 2;      // 0..7
    const int qt = lane & 3;         // 0..3
    float local = 0.f;

    #pragma unroll
    for (int mt = 0; mt < 2; mt++) {
        #pragma unroll
        for (int r2 = 0; r2 < 2; r2++) {            // row half (+0 / +8)
            const int li = wm * 32 + mt * 16 + quad + r2 * 8;
            const int gi = bi * BM + li;
            const float invi = invA_s[li], sqi = sqA_s[li];
            const long long yi = yA_s[li];
            #pragma unroll
            for (int nt = 0; nt < 8; nt++) {
                #pragma unroll
                for (int r1 = 0; r1 < 2; r1++) {    // col within pair
                    const int lj = wn * 64 + nt * 8 + 2 * qt + r1;
                    const int gj = bj * BM + lj;
                    if (gj >= gi) {
                        const float g = c[mt][nt][r2 * 2 + r1] * invi * invB_s[lj];
                        const float dist2 = sqi + sqB_s[lj] - 2.0f * g;
                        const float hinge = fmaxf(1.2f - dist2, 0.0f);
                        local += 0.3f + ((yi == yB_s[lj]) ? hinge : -hinge);
                    }
                }
            }
        }
    }

    #pragma unroll
    for (int o = 16; o; o >>= 1) local += __shfl_xor_sync(0xffffffffu, local, o);
    if (lane == 0) redr[wid] = local;
    __syncthreads();
    if (tid == 0) {
        float s = 0.f;
        #pragma unroll
        for (int i = 0; i < 8; i++) s += redr[i];
        atomicAdd(&g_acc, s);
    }
}

// ---------------------------------------------------------------------------
// Kernel 3: finalize
// ---------------------------------------------------------------------------
__global__ void finalize_kernel(float* out) {
    const double m = 1.0 / ((double)NB * (double)NB - (double)NB);
    out[0] = (float)((double)g_acc * m);
}

extern "C" void kernel_launch(void* const* d_in, const int* in_sizes, int n_in,
                              void* d_out, int out_size) {
    const float* x = (const float*)d_in[0];
    const long long* y = (const long long*)d_in[1];
    float* out = (float*)d_out;

    prep_convert<<<NB / 8, 256>>>(x);
    gemm_loss<<<NPAIR, 256>>>(y);
    finalize_kernel<<<1, 1>>>(out);
}